// round 3
// baseline (speedup 1.0000x reference)
#include <cuda_runtime.h>
#include <cstdint>

#define NTOK   1000000
#define DIMS   128
#define NCLUST 64
#define DK     16      // dim chunk in shared
#define TILE_T 128     // tokens per tile
#define XPAD   132     // padded token stride for x_s rows

typedef unsigned long long u64;

__device__ u64 g_best[NCLUST];

// packed fp32x2 FMA (Blackwell): d = a*b + c on both 32-bit halves.
// Carried in 64-bit integer registers ("l" constraint).
__device__ __forceinline__ u64 ffma2(u64 a, u64 b, u64 c) {
    u64 d;
    asm("fma.rn.f32x2 %0, %1, %2, %3;" : "=l"(d) : "l"(a), "l"(b), "l"(c));
    return d;
}
__device__ __forceinline__ u64 pack2(float lo, float hi) {
    u64 d;
    asm("mov.b64 %0, {%1, %2};" : "=l"(d) : "f"(lo), "f"(hi));
    return d;
}
__device__ __forceinline__ void unpack2(u64 v, float& lo, float& hi) {
    asm("mov.b64 {%0, %1}, %2;" : "=f"(lo), "=f"(hi) : "l"(v));
}
// monotone map: ordered floats -> ordered uints
__device__ __forceinline__ unsigned fkey(float f) {
    unsigned u = __float_as_uint(f);
    return (u & 0x80000000u) ? ~u : (u | 0x80000000u);
}

__global__ void init_kernel() {
    if (threadIdx.x < NCLUST) g_best[threadIdx.x] = 0xFFFFFFFFFFFFFFFFULL;
}

__global__ __launch_bounds__(256, 2)
void cluster_kernel(const float* __restrict__ x, const float* __restrict__ cc) {
    __shared__ float c_s[DIMS][NCLUST];   // 32 KB, transposed C
    __shared__ float x_s[DK][XPAD];       // 8.25 KB, transposed X chunk
    __shared__ float x2_s[TILE_T];        // 0.5 KB

    const int t   = threadIdx.x;
    const int tx  = t & 31;    // token-thread within warp (32 -> 128 tokens)
    const int ty  = t >> 5;    // warp id -> cluster group (8 -> 64 clusters)
    const int tx4 = tx * 4;
    const int ty8 = ty * 8;

    // Load C transposed: c_s[d][n] = cc[n*128 + d]. Coalesced global read;
    // one-time shared-store conflicts are irrelevant.
    for (int i = t; i < NCLUST * DIMS; i += 256) {
        int n = i >> 7, d = i & 127;
        c_s[d][n] = cc[i];
    }
    __syncthreads();

    float    minv[8];
    unsigned mini[8];
#pragma unroll
    for (int j = 0; j < 8; j++) { minv[j] = __int_as_float(0x7F800000); mini[j] = 0u; }

    const int NT = (NTOK + TILE_T - 1) / TILE_T;
    for (int tile = blockIdx.x; tile < NT; tile += gridDim.x) {
        const int tok0 = tile * TILE_T;

        u64 acc[4][4];   // [token][cluster-pair], f32x2 packed (init 0.0f|0.0f = 0ull)
#pragma unroll
        for (int i = 0; i < 4; i++)
#pragma unroll
            for (int p = 0; p < 4; p++) acc[i][p] = 0ull;
        float x2a[4] = {0.f, 0.f, 0.f, 0.f};

        for (int chunk = 0; chunk < DIMS / DK; ++chunk) {
            const int d0 = chunk * DK;
            __syncthreads();   // previous chunk's compute done before overwrite
#pragma unroll
            for (int i = 0; i < (TILE_T * DK) / (256 * 4); ++i) {   // 2 iters
                int linear = t + 256 * i;
                int token  = linear >> 2;       // 0..127
                int f4     = linear & 3;        // 4 float4 per token-row of 16 dims
                int gt     = tok0 + token;
                float4 v = make_float4(0.f, 0.f, 0.f, 0.f);
                if (gt < NTOK)
                    v = *(const float4*)(x + (size_t)gt * DIMS + d0 + f4 * 4);
                x_s[f4 * 4 + 0][token] = v.x;
                x_s[f4 * 4 + 1][token] = v.y;
                x_s[f4 * 4 + 2][token] = v.z;
                x_s[f4 * 4 + 3][token] = v.w;
            }
            __syncthreads();

#pragma unroll
            for (int d = 0; d < DK; ++d) {
                float4 xv = *(const float4*)&x_s[d][tx4];
                ulonglong2 cpA = *(const ulonglong2*)&c_s[d0 + d][ty8];       // (c0,c1),(c2,c3)
                ulonglong2 cpB = *(const ulonglong2*)&c_s[d0 + d][ty8 + 4];   // (c4,c5),(c6,c7)
                u64 xb0 = pack2(xv.x, xv.x);
                u64 xb1 = pack2(xv.y, xv.y);
                u64 xb2 = pack2(xv.z, xv.z);
                u64 xb3 = pack2(xv.w, xv.w);
                acc[0][0] = ffma2(xb0, cpA.x, acc[0][0]);
                acc[0][1] = ffma2(xb0, cpA.y, acc[0][1]);
                acc[0][2] = ffma2(xb0, cpB.x, acc[0][2]);
                acc[0][3] = ffma2(xb0, cpB.y, acc[0][3]);
                acc[1][0] = ffma2(xb1, cpA.x, acc[1][0]);
                acc[1][1] = ffma2(xb1, cpA.y, acc[1][1]);
                acc[1][2] = ffma2(xb1, cpB.x, acc[1][2]);
                acc[1][3] = ffma2(xb1, cpB.y, acc[1][3]);
                acc[2][0] = ffma2(xb2, cpA.x, acc[2][0]);
                acc[2][1] = ffma2(xb2, cpA.y, acc[2][1]);
                acc[2][2] = ffma2(xb2, cpB.x, acc[2][2]);
                acc[2][3] = ffma2(xb2, cpB.y, acc[2][3]);
                acc[3][0] = ffma2(xb3, cpA.x, acc[3][0]);
                acc[3][1] = ffma2(xb3, cpA.y, acc[3][1]);
                acc[3][2] = ffma2(xb3, cpB.x, acc[3][2]);
                acc[3][3] = ffma2(xb3, cpB.y, acc[3][3]);
                if (ty == 0) {   // only warp 0 computes x^2 (shared afterwards)
                    x2a[0] = fmaf(xv.x, xv.x, x2a[0]);
                    x2a[1] = fmaf(xv.y, xv.y, x2a[1]);
                    x2a[2] = fmaf(xv.z, xv.z, x2a[2]);
                    x2a[3] = fmaf(xv.w, xv.w, x2a[3]);
                }
            }
        }

        // epilogue: distribute x2, update running per-cluster minima
        if (ty == 0) {
            x2_s[tx4 + 0] = x2a[0];
            x2_s[tx4 + 1] = x2a[1];
            x2_s[tx4 + 2] = x2a[2];
            x2_s[tx4 + 3] = x2a[3];
        }
        __syncthreads();
        float x2v[4];
#pragma unroll
        for (int i = 0; i < 4; i++) x2v[i] = x2_s[tx4 + i];

#pragma unroll
        for (int i = 0; i < 4; i++) {
            unsigned gt    = (unsigned)(tok0 + tx4 + i);
            bool     valid = gt < NTOK;
#pragma unroll
            for (int p = 0; p < 4; p++) {
                float s0, s1;
                unpack2(acc[i][p], s0, s1);
                float v0 = fmaf(-2.f, s0, x2v[i]);   // d2 - c2 (c2 const per cluster)
                float v1 = fmaf(-2.f, s1, x2v[i]);
                if (valid) {
                    if (v0 < minv[2 * p])     { minv[2 * p]     = v0; mini[2 * p]     = gt; }
                    if (v1 < minv[2 * p + 1]) { minv[2 * p + 1] = v1; mini[2 * p + 1] = gt; }
                }
            }
        }
    }

    // warp-level reduce (all 32 lanes of a warp share the same 8 clusters),
    // then one atomicMin per cluster per block.
#pragma unroll
    for (int j = 0; j < 8; j++) {
        u64 key = ((u64)fkey(minv[j]) << 32) | (u64)mini[j];
#pragma unroll
        for (int off = 16; off > 0; off >>= 1) {
            u64 o = __shfl_down_sync(0xFFFFFFFFu, key, off);
            if (o < key) key = o;
        }
        if (tx == 0) atomicMin(&g_best[ty8 + j], key);
    }
}

__global__ void gather_kernel(const float* __restrict__ x, float* __restrict__ out) {
    int k = blockIdx.x;
    unsigned idx = (unsigned)(g_best[k] & 0xFFFFFFFFULL);
    out[k * DIMS + threadIdx.x] = x[(size_t)idx * DIMS + threadIdx.x];
}

extern "C" void kernel_launch(void* const* d_in, const int* in_sizes, int n_in,
                              void* d_out, int out_size) {
    const float* x  = (const float*)d_in[0];   // (1, 1000000, 128) f32
    const float* cc = (const float*)d_in[1];   // (64, 128) f32
    float* out = (float*)d_out;                // (1, 64, 128) f32

    init_kernel<<<1, 64>>>();
    cluster_kernel<<<304, 256>>>(x, cc);
    gather_kernel<<<NCLUST, DIMS>>>(x, out);
}

// round 11
// speedup vs baseline: 1.2778x; 1.2778x over previous
#include <cuda_runtime.h>
#include <cstdint>

typedef unsigned long long u64;
typedef unsigned int u32;

#define NTOK   1000000
#define DIMS   128
#define NCLUST 64
#define TILE_T 256
#define NTHR   512
#define NWARP  16
#define NBLK   152
#define NT_TILES ((NTOK + TILE_T - 1) / TILE_T)   // 3907

#define XSTR   132                                 // padded float stride per token row
#define SM_X    0
#define SM_BF   (TILE_T * XSTR * 4)                // 135168
#define SM_KEYS (SM_BF + 16 * 8 * 32 * 16)         // +65536 = 200704
#define SM_TOTAL (SM_KEYS + NWARP * NCLUST * 8)    // +8192  = 208896

__device__ u64 g_keys[NBLK * NCLUST];

__device__ __forceinline__ u32 tf32r(float f) {
    u32 r;
    asm("cvt.rna.tf32.f32 %0, %1;" : "=r"(r) : "f"(f));
    return r;
}
__device__ __forceinline__ unsigned fkey(float f) {
    unsigned u = __float_as_uint(f);
    return (u & 0x80000000u) ? ~u : (u | 0x80000000u);
}
// m16n8k8 tf32 mma, D accumulates in place
__device__ __forceinline__ void mma8(float* d, u32 a0, u32 a1, u32 a2, u32 a3,
                                     u32 b0, u32 b1) {
    asm volatile(
        "mma.sync.aligned.m16n8k8.row.col.f32.tf32.tf32.f32 "
        "{%0,%1,%2,%3}, {%4,%5,%6,%7}, {%8,%9}, {%0,%1,%2,%3};"
        : "+f"(d[0]), "+f"(d[1]), "+f"(d[2]), "+f"(d[3])
        : "r"(a0), "r"(a1), "r"(a2), "r"(a3), "r"(b0), "r"(b1));
}

__global__ __launch_bounds__(NTHR, 1)
void cluster_kernel(const float* __restrict__ x, const float* __restrict__ cc) {
    extern __shared__ char sm[];
    float* X    = (float*)(sm + SM_X);
    uint4* BF   = (uint4*)(sm + SM_BF);
    u64*   KEYS = (u64*)(sm + SM_KEYS);

    const int t    = threadIdx.x;
    const int w    = t >> 5;
    const int lane = t & 31;
    const int g    = lane >> 2;   // group id (row within m16 tile)
    const int tg   = lane & 3;    // thread in group (k / n sub-col)
    const int m0   = w << 4;      // this warp's token offset within the tile

    // ---- one-time B-fragment setup: split C into tf32 pieces, fragment-major ----
    // BF[(s*8+n)*32 + lane] = (b0_c1, b1_c1, b0_c2, b1_c2) for that lane's frag slot
    for (int i = t; i < 16 * 8 * 32; i += NTHR) {
        int s = i >> 8, rem = i & 255, n = rem >> 5, ln = rem & 31;
        int gg = ln >> 2, tt = ln & 3;
        int cl = n * 8 + gg;
        int k  = s * 8 + tt;
        float cA = cc[cl * DIMS + k];
        float cB = cc[cl * DIMS + k + 4];
        u32 p1a = tf32r(cA); u32 p2a = tf32r(cA - __uint_as_float(p1a));
        u32 p1b = tf32r(cB); u32 p2b = tf32r(cB - __uint_as_float(p1b));
        BF[i] = make_uint4(p1a, p1b, p2a, p2b);
    }

    float    minv[16];
    unsigned mini[16];
#pragma unroll
    for (int j = 0; j < 16; j++) { minv[j] = __int_as_float(0x7F800000); mini[j] = 0u; }

    for (int tile = blockIdx.x; tile < NT_TILES; tile += NBLK) {
        const int tok0 = tile * TILE_T;
        __syncthreads();   // BF ready (first iter) / previous tile's reads done

        // ---- stage X tile: linear coalesced copy ----
        {
            const float4* src = (const float4*)(x + (size_t)tok0 * DIMS);
#pragma unroll
            for (int i = 0; i < (TILE_T * DIMS) / (NTHR * 4); ++i) {   // 16
                int idx   = t + NTHR * i;          // float4 index within tile
                int token = idx >> 5;              // 32 float4 per token row
                int f4    = idx & 31;
                float4 v = make_float4(0.f, 0.f, 0.f, 0.f);
                if (tok0 + token < NTOK) v = src[idx];
                *(float4*)&X[token * XSTR + f4 * 4] = v;
            }
        }
        __syncthreads();

        // ---- mainloop: 16 k-steps x 8 n-tiles x 3 tf32 passes ----
        float acc[8][4];
#pragma unroll
        for (int n = 0; n < 8; n++)
#pragma unroll
            for (int c = 0; c < 4; c++) acc[n][c] = 0.f;

        const float* Ar0 = &X[(m0 + g) * XSTR];
        const float* Ar1 = Ar0 + 8 * XSTR;
#pragma unroll
        for (int s = 0; s < 16; s++) {
            const int k0 = s * 8;
            float xa0 = Ar0[k0 + tg],     xa2 = Ar0[k0 + tg + 4];
            float xb0 = Ar1[k0 + tg],     xb2 = Ar1[k0 + tg + 4];
            // piece 1 (tf32 of x) and piece 2 (tf32 of residual)
            u32 p1_0 = tf32r(xa0); u32 p2_0 = tf32r(xa0 - __uint_as_float(p1_0));
            u32 p1_1 = tf32r(xb0); u32 p2_1 = tf32r(xb0 - __uint_as_float(p1_1));
            u32 p1_2 = tf32r(xa2); u32 p2_2 = tf32r(xa2 - __uint_as_float(p1_2));
            u32 p1_3 = tf32r(xb2); u32 p2_3 = tf32r(xb2 - __uint_as_float(p1_3));
            const uint4* bf = &BF[(s * 8) * 32 + lane];
#pragma unroll
            for (int n = 0; n < 8; n++) {
                uint4 bv = bf[n * 32];
                mma8(acc[n], p1_0, p1_1, p1_2, p1_3, bv.x, bv.y);   // x1*c1
                mma8(acc[n], p1_0, p1_1, p1_2, p1_3, bv.z, bv.w);   // x1*c2
                mma8(acc[n], p2_0, p2_1, p2_2, p2_3, bv.x, bv.y);   // x2*c1
            }
        }

        // ---- epilogue: full-row x^2 for this lane's two tokens ----
        // Per warp: 4 lanes broadcast per row; rows at bank offsets 4g..4g+3
        // -> conflict-free LDS.128.
        float x20 = 0.f, x21 = 0.f;
#pragma unroll
        for (int i = 0; i < 32; i++) {   // 32 float4 = 128 floats
            float4 v = *(const float4*)&Ar0[i * 4];
            x20 = fmaf(v.x, v.x, x20); x20 = fmaf(v.y, v.y, x20);
            x20 = fmaf(v.z, v.z, x20); x20 = fmaf(v.w, v.w, x20);
            float4 u = *(const float4*)&Ar1[i * 4];
            x21 = fmaf(u.x, u.x, x21); x21 = fmaf(u.y, u.y, x21);
            x21 = fmaf(u.z, u.z, x21); x21 = fmaf(u.w, u.w, x21);
        }

        const unsigned r0 = (unsigned)(tok0 + m0 + g);
        const unsigned r1 = r0 + 8;
        const bool v0 = r0 < NTOK, v1 = r1 < NTOK;
#pragma unroll
        for (int n = 0; n < 8; n++) {
            float d0 = fmaf(-2.f, acc[n][0], x20);   // (r0, cluster 8n+2tg)
            float d1 = fmaf(-2.f, acc[n][1], x20);   // (r0, cluster 8n+2tg+1)
            float d2 = fmaf(-2.f, acc[n][2], x21);   // (r1, cluster 8n+2tg)
            float d3 = fmaf(-2.f, acc[n][3], x21);   // (r1, cluster 8n+2tg+1)
            if (v0) {
                if (d0 < minv[2 * n])     { minv[2 * n]     = d0; mini[2 * n]     = r0; }
                if (d1 < minv[2 * n + 1]) { minv[2 * n + 1] = d1; mini[2 * n + 1] = r0; }
            }
            if (v1) {
                if (d2 < minv[2 * n])     { minv[2 * n]     = d2; mini[2 * n]     = r1; }
                if (d3 < minv[2 * n + 1]) { minv[2 * n + 1] = d3; mini[2 * n + 1] = r1; }
            }
        }
    }

    // ---- reduce: lanes sharing tg hold the same 16 clusters ----
#pragma unroll
    for (int j = 0; j < 16; j++) {
        u64 key = ((u64)fkey(minv[j]) << 32) | (u64)mini[j];
        u64 o;
        o = __shfl_down_sync(0xFFFFFFFFu, key, 16); if (o < key) key = o;
        o = __shfl_down_sync(0xFFFFFFFFu, key, 8);  if (o < key) key = o;
        o = __shfl_down_sync(0xFFFFFFFFu, key, 4);  if (o < key) key = o;
        if (lane < 4)
            KEYS[w * NCLUST + (j >> 1) * 8 + 2 * lane + (j & 1)] = key;
    }
    __syncthreads();
    if (t < NCLUST) {
        u64 k = KEYS[t];
#pragma unroll
        for (int ww = 1; ww < NWARP; ww++) {
            u64 o = KEYS[ww * NCLUST + t];
            if (o < k) k = o;
        }
        g_keys[blockIdx.x * NCLUST + t] = k;
    }
}

__global__ void gather_kernel(const float* __restrict__ x, float* __restrict__ out) {
    __shared__ u64 red[128];
    const int t = threadIdx.x, k = blockIdx.x;
    u64 best = 0xFFFFFFFFFFFFFFFFULL;
    for (int b = t; b < NBLK; b += 128) {
        u64 o = g_keys[b * NCLUST + k];
        if (o < best) best = o;
    }
    red[t] = best;
    __syncthreads();
    for (int s = 64; s > 0; s >>= 1) {
        if (t < s) { u64 o = red[t + s]; if (o < red[t]) red[t] = o; }
        __syncthreads();
    }
    unsigned idx = (unsigned)(red[0] & 0xFFFFFFFFULL);
    out[k * DIMS + t] = x[(size_t)idx * DIMS + t];
}

extern "C" void kernel_launch(void* const* d_in, const int* in_sizes, int n_in,
                              void* d_out, int out_size) {
    const float* x  = (const float*)d_in[0];   // (1, 1000000, 128) f32
    const float* cc = (const float*)d_in[1];   // (64, 128) f32
    float* out = (float*)d_out;                // (1, 64, 128) f32

    cudaFuncSetAttribute(cluster_kernel,
                         cudaFuncAttributeMaxDynamicSharedMemorySize, SM_TOTAL);
    cluster_kernel<<<NBLK, NTHR, SM_TOTAL>>>(x, cc);
    gather_kernel<<<NCLUST, DIMS>>>(x, out);
}

// round 14
// speedup vs baseline: 2.0606x; 1.6126x over previous
#include <cuda_runtime.h>
#include <cstdint>

typedef unsigned long long u64;
typedef unsigned int u32;

#define NTOK   1000000
#define DIMS   128
#define NCLUST 64
#define TILE_T 128
#define NTHR   512
#define NWARP  16
#define NBLK   152
#define NT_TILES ((NTOK + TILE_T - 1) / TILE_T)   // 7813

#define XSTR    132                       // padded float stride per token row
#define XBYTES  (TILE_T * XSTR * 4)       // 67584
#define SM_X0   0
#define SM_X1   XBYTES
#define SM_BF   (2 * XBYTES)              // 135168: 8s x 8n x 32 lanes x uint4
#define SM_KEYS (SM_BF + 8 * 8 * 32 * 16) // 167936: 16 warps x 32 clusters x u64
#define SM_TOTAL (SM_KEYS + NWARP * 32 * 8)   // 172032

__device__ u64 g_keys[NBLK * NCLUST];

// ---- helpers ----
__device__ __forceinline__ unsigned fkey(float f) {
    unsigned u = __float_as_uint(f);
    return (u & 0x80000000u) ? ~u : (u | 0x80000000u);
}
// pack two f32 -> f16x2 (lo = first arg)
__device__ __forceinline__ u32 f2h2(float lo, float hi) {
    u32 r;
    asm("cvt.rn.f16x2.f32 %0, %1, %2;" : "=r"(r) : "f"(hi), "f"(lo));
    return r;
}
__device__ __forceinline__ void h2tof(u32 h, float& lo, float& hi) {
    asm("{ .reg .f16 l, m; mov.b32 {l, m}, %2;\n\t"
        "cvt.f32.f16 %0, l; cvt.f32.f16 %1, m; }"
        : "=f"(lo), "=f"(hi) : "r"(h));
}
// m16n8k16 f16 mma, fp32 accumulate in place
__device__ __forceinline__ void mma16(float* d, u32 a0, u32 a1, u32 a2, u32 a3,
                                      u32 b0, u32 b1) {
    asm volatile(
        "mma.sync.aligned.m16n8k16.row.col.f32.f16.f16.f32 "
        "{%0,%1,%2,%3}, {%4,%5,%6,%7}, {%8,%9}, {%0,%1,%2,%3};"
        : "+f"(d[0]), "+f"(d[1]), "+f"(d[2]), "+f"(d[3])
        : "r"(a0), "r"(a1), "r"(a2), "r"(a3), "r"(b0), "r"(b1));
}
__device__ __forceinline__ u32 smem_u32(const void* p) {
    return (u32)__cvta_generic_to_shared(p);
}

__global__ __launch_bounds__(NTHR, 1)
void cluster_kernel(const float* __restrict__ x, const float* __restrict__ cc) {
    extern __shared__ char sm[];
    float* XB[2] = { (float*)(sm + SM_X0), (float*)(sm + SM_X1) };
    uint4* BF    = (uint4*)(sm + SM_BF);
    u64*   KEYS  = (u64*)(sm + SM_KEYS);

    const int t    = threadIdx.x;
    const int w    = t >> 5;
    const int lane = t & 31;
    const int g    = lane >> 2;   // row-in-tile group / B n-index
    const int tg   = lane & 3;    // k sub-slot
    const int mt   = w >> 1;      // m-tile 0..7 (16 tokens each)
    const int nh   = w & 1;       // n-half (32 clusters each)

    // ---- prefetch helper (cp.async, 16B, zero-fill OOB) ----
    auto prefetch = [&](int tok0, int buf) {
        const float4* src = (const float4*)(x + (size_t)tok0 * DIMS);
        u32 dbase = smem_u32(XB[buf]);
#pragma unroll
        for (int i = 0; i < (TILE_T * DIMS) / (NTHR * 4); ++i) {   // 8
            int idx   = t + NTHR * i;
            int token = idx >> 5;
            int f4    = idx & 31;
            u32 dst   = dbase + (u32)(token * XSTR + f4 * 4) * 4u;
            int valid = (tok0 + token < NTOK) ? 16 : 0;
            const float4* s = src + (valid ? idx : 0);
            asm volatile("cp.async.cg.shared.global [%0], [%1], 16, %2;"
                         :: "r"(dst), "l"(s), "r"(valid));
        }
    };

    // first tile prefetch, then B-fragment setup overlapping the copy
    int tile0 = blockIdx.x;
    if (tile0 < NT_TILES) prefetch(tile0 * TILE_T, 0);
    asm volatile("cp.async.commit_group;");

    // ---- one-time B fragments: fp16 split, fragment-major ----
    // BF[(s*8+n)*32 + lane] = (b0_h1, b1_h1, b0_h2, b1_h2)
    // lane's k-slots remapped: data k = s*16 + 4*tg + {0..3} (A uses same map)
    for (int i = t; i < 8 * 8 * 32; i += NTHR) {
        int s = i >> 8, n = (i >> 5) & 7, ln = i & 31;
        int gg = ln >> 2, tt = ln & 3;
        int cl = n * 8 + gg;
        const float* cp = cc + cl * DIMS + s * 16 + 4 * tt;
        float c0 = cp[0], c1 = cp[1], c2 = cp[2], c3 = cp[3];
        u32 p1a = f2h2(c0, c1), p1b = f2h2(c2, c3);
        float f0, f1, f2, f3;
        h2tof(p1a, f0, f1); h2tof(p1b, f2, f3);
        u32 p2a = f2h2(c0 - f0, c1 - f1), p2b = f2h2(c2 - f2, c3 - f3);
        BF[i] = make_uint4(p1a, p1b, p2a, p2b);
    }

    float    minv[8];
    unsigned mini[8];
#pragma unroll
    for (int j = 0; j < 8; j++) { minv[j] = __int_as_float(0x7F800000); mini[j] = 0u; }

    int p = 0;
    for (int tile = tile0; tile < NT_TILES; tile += NBLK) {
        const int tok0 = tile * TILE_T;
        const int nxt  = tile + NBLK;
        if (nxt < NT_TILES) prefetch(nxt * TILE_T, 1 - p);
        asm volatile("cp.async.commit_group;");
        asm volatile("cp.async.wait_group 1;");
        __syncthreads();   // current buffer (and BF on first iter) visible

        const float* X   = XB[p];
        const float* Ar0 = &X[(mt * 16 + g) * XSTR];
        const float* Ar1 = Ar0 + 8 * XSTR;

        float acc[4][4];
#pragma unroll
        for (int n = 0; n < 4; n++)
#pragma unroll
            for (int c = 0; c < 4; c++) acc[n][c] = 0.f;
        float x20 = 0.f, x21 = 0.f;

#pragma unroll
        for (int s = 0; s < 8; s++) {
            float4 va = *(const float4*)&Ar0[s * 16 + 4 * tg];
            float4 vb = *(const float4*)&Ar1[s * 16 + 4 * tg];
            x20 = fmaf(va.x, va.x, x20); x20 = fmaf(va.y, va.y, x20);
            x20 = fmaf(va.z, va.z, x20); x20 = fmaf(va.w, va.w, x20);
            x21 = fmaf(vb.x, vb.x, x21); x21 = fmaf(vb.y, vb.y, x21);
            x21 = fmaf(vb.z, vb.z, x21); x21 = fmaf(vb.w, vb.w, x21);
            // fp16 piece 1
            u32 a0 = f2h2(va.x, va.y), a2 = f2h2(va.z, va.w);
            u32 a1 = f2h2(vb.x, vb.y), a3 = f2h2(vb.z, vb.w);
            // residual piece 2
            float f0, f1, f2, f3, h0, h1, h2, h3;
            h2tof(a0, f0, f1); h2tof(a2, f2, f3);
            h2tof(a1, h0, h1); h2tof(a3, h2, h3);
            u32 r0 = f2h2(va.x - f0, va.y - f1), r2 = f2h2(va.z - f2, va.w - f3);
            u32 r1 = f2h2(vb.x - h0, vb.y - h1), r3 = f2h2(vb.z - h2, vb.w - h3);

            const uint4* bf = &BF[(s * 8 + nh * 4) * 32 + lane];
#pragma unroll
            for (int n = 0; n < 4; n++) {
                uint4 bv = bf[n * 32];
                mma16(acc[n], a0, a1, a2, a3, bv.x, bv.y);   // x1*c1
                mma16(acc[n], a0, a1, a2, a3, bv.z, bv.w);   // x1*c2
                mma16(acc[n], r0, r1, r2, r3, bv.x, bv.y);   // x2*c1
            }
        }

        // full-row x^2: sum over the 4-lane tg group
        x20 += __shfl_xor_sync(0xFFFFFFFFu, x20, 1);
        x20 += __shfl_xor_sync(0xFFFFFFFFu, x20, 2);
        x21 += __shfl_xor_sync(0xFFFFFFFFu, x21, 1);
        x21 += __shfl_xor_sync(0xFFFFFFFFu, x21, 2);

        const unsigned tr0 = (unsigned)(tok0 + mt * 16 + g);
        const unsigned tr1 = tr0 + 8;
        const bool v0 = tr0 < NTOK, v1 = tr1 < NTOK;
#pragma unroll
        for (int n = 0; n < 4; n++) {
            float d0 = fmaf(-2.f, acc[n][0], x20);
            float d1 = fmaf(-2.f, acc[n][1], x20);
            float d2 = fmaf(-2.f, acc[n][2], x21);
            float d3 = fmaf(-2.f, acc[n][3], x21);
            if (v0) {
                if (d0 < minv[2 * n])     { minv[2 * n]     = d0; mini[2 * n]     = tr0; }
                if (d1 < minv[2 * n + 1]) { minv[2 * n + 1] = d1; mini[2 * n + 1] = tr0; }
            }
            if (v1) {
                if (d2 < minv[2 * n])     { minv[2 * n]     = d2; mini[2 * n]     = tr1; }
                if (d3 < minv[2 * n + 1]) { minv[2 * n + 1] = d3; mini[2 * n + 1] = tr1; }
            }
        }
        __syncthreads();   // all reads of XB[p] done before it is re-filled
        p ^= 1;
    }

    // ---- warp reduce over g (lanes sharing tg hold same 8 clusters) ----
#pragma unroll
    for (int j = 0; j < 8; j++) {
        u64 key = ((u64)fkey(minv[j]) << 32) | (u64)mini[j];
        u64 o;
        o = __shfl_down_sync(0xFFFFFFFFu, key, 16); if (o < key) key = o;
        o = __shfl_down_sync(0xFFFFFFFFu, key, 8);  if (o < key) key = o;
        o = __shfl_down_sync(0xFFFFFFFFu, key, 4);  if (o < key) key = o;
        if (lane < 4)
            KEYS[w * 32 + (j >> 1) * 8 + 2 * lane + (j & 1)] = key;
    }
    __syncthreads();
    // block reduce: cluster t = nh*32 + local; warps 2j+nh cover that half
    if (t < NCLUST) {
        int nht = t >> 5, loc = t & 31;
        u64 k = KEYS[nht * 32 + loc];
#pragma unroll
        for (int j = 1; j < 8; j++) {
            u64 o = KEYS[(2 * j + nht) * 32 + loc];
            if (o < k) k = o;
        }
        g_keys[blockIdx.x * NCLUST + t] = k;
    }
}

__global__ void gather_kernel(const float* __restrict__ x, float* __restrict__ out) {
    __shared__ u64 red[128];
    const int t = threadIdx.x, k = blockIdx.x;
    u64 best = 0xFFFFFFFFFFFFFFFFULL;
    for (int b = t; b < NBLK; b += 128) {
        u64 o = g_keys[b * NCLUST + k];
        if (o < best) best = o;
    }
    red[t] = best;
    __syncthreads();
    for (int s = 64; s > 0; s >>= 1) {
        if (t < s) { u64 o = red[t + s]; if (o < red[t]) red[t] = o; }
        __syncthreads();
    }
    unsigned idx = (unsigned)(red[0] & 0xFFFFFFFFULL);
    out[k * DIMS + t] = x[(size_t)idx * DIMS + t];
}

extern "C" void kernel_launch(void* const* d_in, const int* in_sizes, int n_in,
                              void* d_out, int out_size) {
    const float* x  = (const float*)d_in[0];   // (1, 1000000, 128) f32
    const float* cc = (const float*)d_in[1];   // (64, 128) f32
    float* out = (float*)d_out;                // (1, 64, 128) f32

    cudaFuncSetAttribute(cluster_kernel,
                         cudaFuncAttributeMaxDynamicSharedMemorySize, SM_TOTAL);
    cluster_kernel<<<NBLK, NTHR, SM_TOTAL>>>(x, cc);
    gather_kernel<<<NCLUST, DIMS>>>(x, out);
}